// round 10
// baseline (speedup 1.0000x reference)
#include <cuda_runtime.h>
#include <cuda_fp16.h>

#define L 2048
#define CIN 16
#define GROUPS 4
#define LS 2056              // padded scratch row stride in HALVES: 4 lead + 2048 + 4 trail
#define ROWS_P (L + 2)       // +1 zero guard row above and below per channel

// ~135 MiB fp16 scratch. Channel c, padded row r holds data row r-1 (rows 0
// and L+1 zero guards). Cols: [0,4) lead pad, [4,4+L) data, trail pad.
// Above-diagonal cols zero-filled through the last 512-tile any conv consumer
// reads, so conv staging is fully branch-free.
__device__ __half g_probs[(size_t)CIN * ROWS_P * LS];

// ---- packed f32x2 helpers (sm_10x) ----
__device__ __forceinline__ unsigned long long pk2(float a, float b) {
    unsigned long long r;
    asm("mov.b64 %0, {%1, %2};" : "=l"(r) : "f"(a), "f"(b));
    return r;
}
__device__ __forceinline__ void upk2(unsigned long long p, float& a, float& b) {
    asm("mov.b64 {%0, %1}, %2;" : "=f"(a), "=f"(b) : "l"(p));
}
__device__ __forceinline__ void fma2(unsigned long long& d,
                                     unsigned long long a, unsigned long long b) {
    asm("fma.rn.f32x2 %0, %1, %2, %0;" : "+l"(d) : "l"(a), "l"(b));
}

// ---------------------------------------------------------------------------
// Kernel 1: causal sparsemax, ONE WARP PER ROW.
// 16 back-to-back predicated LDG.128 (MLP ~16); Michelot fixed point from
// tight tau0 = max((S-1)/n, max-1); shfl reductions; vectorized store+fill.
// ---------------------------------------------------------------------------
__global__ void __launch_bounds__(256) sparsemax_rows(const float* __restrict__ scores) {
    const int tid  = threadIdx.x;
    const int w    = tid >> 5;
    const int lane = tid & 31;
    const int i    = (blockIdx.x << 3) + w;   // data row
    const int c    = blockIdx.y;              // channel
    const int n    = i + 1;                   // valid prefix length

    const float* src = scores + ((size_t)c * L + (size_t)i) * L;
    __half* dst = g_probs + ((size_t)c * ROWS_P + (size_t)(i + 1)) * LS + 4;

    const int full = n >> 7;        // chunks [0,full) fully valid (128 cols each)
    const int base = lane << 2;

    float z[64];
    // branch-free predicated load pass: 16 consecutive @P LDG.128
#pragma unroll
    for (int t = 0; t < 16; t++) {
        if (t <= full) {
            *reinterpret_cast<float4*>(&z[4 * t]) =
                *reinterpret_cast<const float4*>(src + (t << 7) + base);
        }
    }
    // mask the partial chunk (static register indices; warp-uniform branch)
#pragma unroll
    for (int t = 0; t < 16; t++) {
        if (t == full) {
#pragma unroll
            for (int q = 0; q < 4; q++)
                if ((t << 7) + base + q >= n) z[4 * t + q] = -3.0e38f;
        }
    }

    // register-only sum + max pass
    float S = 0.f, M = -3.0e38f;
#pragma unroll
    for (int t = 0; t < 16; t++) {
        if (t > full) break;            // warp-uniform
#pragma unroll
        for (int q = 0; q < 4; q++) {
            float zz = z[4 * t + q];
            if (zz > -3.0e38f) S += zz;
            M = fmaxf(M, zz);
        }
    }
#pragma unroll
    for (int o = 16; o; o >>= 1) {
        S += __shfl_xor_sync(0xffffffffu, S, o);
        M = fmaxf(M, __shfl_xor_sync(0xffffffffu, M, o));
    }

    // tight start: tau* >= zmax - 1
    float tau = fmaxf((S - 1.0f) / (float)n, M - 1.0f);
    float kprev = 3.0e38f;   // no break before first tau update

#pragma unroll 1
    for (int it = 0; it < 64; ++it) {
        float ls = 0.f, lc = 0.f;
#pragma unroll
        for (int t = 0; t < 16; t++) {
            if (t > full) break;        // warp-uniform
#pragma unroll
            for (int q = 0; q < 4; q++) {
                float zz = z[4 * t + q];
                if (zz > tau) { ls += zz; lc += 1.f; }
            }
        }
#pragma unroll
        for (int o = 16; o; o >>= 1) {
            ls += __shfl_xor_sync(0xffffffffu, ls, o);
            lc += __shfl_xor_sync(0xffffffffu, lc, o);
        }
        if (lc >= kprev || lc == 0.f) break;   // support stable -> fixed point
        tau = (ls - 1.0f) / lc;
        kprev = lc;
    }

    // combined store + zero-fill pass (uint2 = 4 halves per lane-chunk)
    const int E  = min(2052, ((((n + 1) >> 9) << 9) + 516));
    const int EC = (E + 127) >> 7;
#pragma unroll
    for (int t = 0; t < 16; t++) {
        if (t < full) {
            __half2 h0 = __floats2half2_rn(fmaxf(z[4 * t + 0] - tau, 0.f),
                                           fmaxf(z[4 * t + 1] - tau, 0.f));
            __half2 h1 = __floats2half2_rn(fmaxf(z[4 * t + 2] - tau, 0.f),
                                           fmaxf(z[4 * t + 3] - tau, 0.f));
            uint2 pk;
            pk.x = *reinterpret_cast<unsigned*>(&h0);
            pk.y = *reinterpret_cast<unsigned*>(&h1);
            *reinterpret_cast<uint2*>(dst + (t << 7) + base) = pk;
        } else if (t == full) {
            float p0 = ((t << 7) + base + 0 < n) ? fmaxf(z[4 * t + 0] - tau, 0.f) : 0.f;
            float p1 = ((t << 7) + base + 1 < n) ? fmaxf(z[4 * t + 1] - tau, 0.f) : 0.f;
            float p2 = ((t << 7) + base + 2 < n) ? fmaxf(z[4 * t + 2] - tau, 0.f) : 0.f;
            float p3 = ((t << 7) + base + 3 < n) ? fmaxf(z[4 * t + 3] - tau, 0.f) : 0.f;
            __half2 h0 = __floats2half2_rn(p0, p1);
            __half2 h1 = __floats2half2_rn(p2, p3);
            uint2 pk;
            pk.x = *reinterpret_cast<unsigned*>(&h0);
            pk.y = *reinterpret_cast<unsigned*>(&h1);
            *reinterpret_cast<uint2*>(dst + (t << 7) + base) = pk;
        } else if (t < EC) {
            *reinterpret_cast<uint2*>(dst + (t << 7) + base) = make_uint2(0u, 0u);
        }
    }
    if (lane == 0) {
        *reinterpret_cast<uint2*>(dst - 4) = make_uint2(0u, 0u);
        if (E > 2048) *reinterpret_cast<uint2*>(dst + 2048) = make_uint2(0u, 0u);
    }
    if (i == 0) {
        uint4* gr = reinterpret_cast<uint4*>(g_probs + (size_t)c * ROWS_P * LS);
        const uint4 z4 = make_uint4(0u, 0u, 0u, 0u);
        for (int j = lane; j < LS / 8; j += 32) gr[j] = z4;
    }
    if (i == L - 1) {
        uint4* gr = reinterpret_cast<uint4*>(
            g_probs + ((size_t)c * ROWS_P + (size_t)(L + 1)) * LS);
        const uint4 z4 = make_uint4(0u, 0u, 0u, 0u);
        for (int j = lane; j < LS / 8; j += 32) gr[j] = z4;
    }
}

// ---------------------------------------------------------------------------
// Kernel 2: grouped 3x3 conv + bias + causal zero, TWO output rows per block.
// Inner math in PACKED f32x2 FMA (halves FMA issue): output cols paired
// (q0,q1)/(q2,q3); weights pre-duplicated {w,w} in smem (LDS.64 broadcast).
// grid = (4 tiles of 512, L/2 row-pairs, 4 groups), 128 threads.
// ---------------------------------------------------------------------------
__global__ void __launch_bounds__(128) conv3x3_group(const float* __restrict__ weight,
                                                     const float* __restrict__ bias,
                                                     float* __restrict__ out) {
    const int g   = blockIdx.z;
    const int i0  = blockIdx.y * 2;
    const int j0  = blockIdx.x * 512;
    const int tid = threadIdx.x;

    if (j0 > i0 + 1) {  // both rows entirely above diagonal -> zeros
        const float4 z4 = make_float4(0.f, 0.f, 0.f, 0.f);
#pragma unroll
        for (int ro = 0; ro < 2; ro++)
#pragma unroll
            for (int co = 0; co < 4; co++) {
                size_t o = ((size_t)(g * 4 + co) * L + (size_t)(i0 + ro)) * L
                         + (size_t)(j0 + tid * 4);
                *reinterpret_cast<float4*>(out + o) = z4;
            }
        return;
    }

    __shared__ float s_in[16][528];              // fp32 planes, stride-pad 528
    __shared__ unsigned long long s_w2[144];     // {w,w} duplicated pairs
    __shared__ float s_b[4];

    for (int e = tid; e < 144; e += 128) {
        float wv = weight[g * 144 + e];
        s_w2[e] = pk2(wv, wv);
    }
    if (tid < 4) s_b[tid] = bias[g * 4 + tid];

    // staging: LDG.64 of 4 halves -> convert -> STS.128 float4. 130 per plane.
#pragma unroll
    for (int u = 0; u < 4; u++) {
#pragma unroll
        for (int r = 0; r < 4; r++) {
            const uint2* src = reinterpret_cast<const uint2*>(
                g_probs + ((size_t)(g * 4 + u) * ROWS_P + (size_t)(i0 + r)) * LS + (size_t)j0);
            float4* dp = reinterpret_cast<float4*>(&s_in[u * 4 + r][0]);
            {
                uint2 v = src[tid];
                float2 f0 = __half22float2(*reinterpret_cast<__half2*>(&v.x));
                float2 f1 = __half22float2(*reinterpret_cast<__half2*>(&v.y));
                dp[tid] = make_float4(f0.x, f0.y, f1.x, f1.y);
            }
            if (tid < 2) {
                uint2 v = src[128 + tid];
                float2 f0 = __half22float2(*reinterpret_cast<__half2*>(&v.x));
                float2 f1 = __half22float2(*reinterpret_cast<__half2*>(&v.y));
                dp[128 + tid] = make_float4(f0.x, f0.y, f1.x, f1.y);
            }
        }
    }
    __syncthreads();

    // packed accumulators: acc01 = (q0,q1), acc23 = (q2,q3)
    unsigned long long acc01[2][4], acc23[2][4];
#pragma unroll
    for (int ro = 0; ro < 2; ro++)
#pragma unroll
        for (int co = 0; co < 4; co++) {
            unsigned long long b2 = pk2(s_b[co], s_b[co]);
            acc01[ro][co] = b2;
            acc23[ro][co] = b2;
        }

#pragma unroll
    for (int u = 0; u < 4; u++) {
        // packed sliding-window pairs per input row: P[r][m] = {v_m, v_{m+1}}
        unsigned long long P[4][5];
#pragma unroll
        for (int r = 0; r < 4; r++) {
            const float4* rowp = reinterpret_cast<const float4*>(&s_in[u * 4 + r][0]);
            const float4 a = rowp[tid];
            const float4 b = rowp[tid + 1];
            const float4 cc = rowp[tid + 2];
            const float v0 = a.w, v1 = b.x, v2 = b.y, v3 = b.z, v4 = b.w, v5 = cc.x;
            P[r][0] = pk2(v0, v1);
            P[r][1] = pk2(v1, v2);
            P[r][2] = pk2(v2, v3);
            P[r][3] = pk2(v3, v4);
            P[r][4] = pk2(v4, v5);
        }
#pragma unroll
        for (int ro = 0; ro < 2; ro++) {
#pragma unroll
            for (int kh = 0; kh < 3; kh++) {
                const unsigned long long* p = P[ro + kh];
#pragma unroll
                for (int co = 0; co < 4; co++) {
                    const unsigned long long w0 = s_w2[co * 36 + u * 9 + kh * 3 + 0];
                    const unsigned long long w1 = s_w2[co * 36 + u * 9 + kh * 3 + 1];
                    const unsigned long long w2 = s_w2[co * 36 + u * 9 + kh * 3 + 2];
                    fma2(acc01[ro][co], p[0], w0);
                    fma2(acc01[ro][co], p[1], w1);
                    fma2(acc01[ro][co], p[2], w2);
                    fma2(acc23[ro][co], p[2], w0);
                    fma2(acc23[ro][co], p[3], w1);
                    fma2(acc23[ro][co], p[4], w2);
                }
            }
        }
    }

    const int colb = j0 + tid * 4;
#pragma unroll
    for (int ro = 0; ro < 2; ro++) {
        const int ii = i0 + ro;
#pragma unroll
        for (int co = 0; co < 4; co++) {
            float4 r4;
            upk2(acc01[ro][co], r4.x, r4.y);
            upk2(acc23[ro][co], r4.z, r4.w);
            r4.x = (colb + 0 <= ii) ? r4.x : 0.f;
            r4.y = (colb + 1 <= ii) ? r4.y : 0.f;
            r4.z = (colb + 2 <= ii) ? r4.z : 0.f;
            r4.w = (colb + 3 <= ii) ? r4.w : 0.f;
            size_t o = ((size_t)(g * 4 + co) * L + (size_t)ii) * L + (size_t)colb;
            *reinterpret_cast<float4*>(out + o) = r4;
        }
    }
}

extern "C" void kernel_launch(void* const* d_in, const int* in_sizes, int n_in,
                              void* d_out, int out_size) {
    const float* scores = (const float*)d_in[0];
    const float* weight = (const float*)d_in[1];
    const float* bias   = (const float*)d_in[2];
    float* out = (float*)d_out;

    sparsemax_rows<<<dim3(L / 8, CIN), 256>>>(scores);
    conv3x3_group<<<dim3(L / 512, L / 2, GROUPS), 128>>>(weight, bias, out);
}